// round 11
// baseline (speedup 1.0000x reference)
#include <cuda_runtime.h>
#include <cuda_fp16.h>

#define N_NODES 50000
#define N_EDGES 800000
#define IN_CH   128
#define HID     128
#define OUT_CH  64
#define NCHUNK  ((N_NODES + 255) / 256)   // 196

// ---------------- device-global scratch ------------------------------------
__device__ float  g_W12[IN_CH * OUT_CH];             // W1 @ W2  (128x64)
__device__ __half g_Gsh [(size_t)N_NODES * OUT_CH];  // fp16(dinv .* (x@W12))
__device__ __half g_h2sh[(size_t)N_NODES * OUT_CH];  // fp16(dinv .* h2)
__device__ float  g_c[OUT_CH];                       // b1^T @ W2
__device__ float  g_dinv[N_NODES];
__device__ int    g_cnt[N_NODES];                    // in-degree (self-cleaning)
__device__ int    g_pos[N_NODES];                    // placement cursor
__device__ int    g_row_start[N_NODES + 1];
__device__ int    g_csr_src[N_EDGES];
__device__ int    g_agg[NCHUNK];
__device__ volatile int g_flag[NCHUNK];              // cleared in count_deg

// ---------------- count: 4 edges/thread; block 0 clears scan flags ----------
__global__ void count_deg_kernel(const int* __restrict__ dst) {
    int t = blockIdx.x * blockDim.x + threadIdx.x;
    if (blockIdx.x == 0 && threadIdx.x < NCHUNK) g_flag[threadIdx.x] = 0;
    if (t < N_EDGES / 4) {
        int4 d = *(const int4*)(dst + t * 4);
        atomicAdd(&g_cnt[d.x], 1);
        atomicAdd(&g_cnt[d.y], 1);
        atomicAdd(&g_cnt[d.z], 1);
        atomicAdd(&g_cnt[d.w], 1);
    }
}

// ---------------- w12: split-K, one block per output row -------------------
// Block k in [0,128): W12[k][:] = W1[k,:] @ W2.  Block 128: c = b1 @ W2.
// 256 threads: j = tid&63, q = tid>>6 handles K chunk [q*32, q*32+32).
__global__ void w12_kernel(const float* __restrict__ W1,
                           const float* __restrict__ W2,
                           const float* __restrict__ b1) {
    __shared__ float part[4][OUT_CH];
    const int k = blockIdx.x;            // 0..128
    const int j = threadIdx.x & 63;
    const int q = threadIdx.x >> 6;      // 0..3
    const float* row = (k < IN_CH) ? (W1 + (size_t)k * HID) : b1;

    float s = 0.f;
#pragma unroll
    for (int t = 0; t < 32; t++) {
        int kk = q * 32 + t;
        s += __ldg(&row[kk]) * __ldg(&W2[(size_t)kk * OUT_CH + j]);
    }
    part[q][j] = s;
    __syncthreads();
    if (q == 0) {
        float v = part[0][j] + part[1][j] + part[2][j] + part[3][j];
        if (k < IN_CH) g_W12[k * OUT_CH + j] = v;
        else           g_c[j] = v;
    }
}

// ---------------- fused single-pass scan (publish-all, wait-all) -----------
__global__ void scan_fused_kernel() {
    __shared__ int s[256];
    __shared__ int pre[256];
    const int tid = threadIdx.x;
    const int chunk = blockIdx.x;
    const int i = chunk * 256 + tid;

    int val = (i < N_NODES) ? g_cnt[i] : 0;
    if (i < N_NODES) g_cnt[i] = 0;        // self-clean for next replay
    s[tid] = val;
    __syncthreads();
#pragma unroll
    for (int off = 1; off < 256; off <<= 1) {
        int t = (tid >= off) ? s[tid - off] : 0;
        __syncthreads();
        s[tid] += t;
        __syncthreads();
    }
    int incl = s[tid];

    if (tid == 0) {
        g_agg[chunk] = s[255];
        __threadfence();
        g_flag[chunk] = 1;
    }

    int my = 0;
    if (tid < chunk) {
        while (g_flag[tid] == 0) { }
        __threadfence();
        my = g_agg[tid];
    }
    __syncthreads();
    pre[tid] = my;
    __syncthreads();
#pragma unroll
    for (int off = 128; off > 0; off >>= 1) {
        if (tid < off) pre[tid] += pre[tid + off];
        __syncthreads();
    }
    int chunk_off = pre[0];

    if (i < N_NODES) {
        int rs = chunk_off + incl - val;
        g_row_start[i] = rs;
        g_pos[i]       = rs;
        g_dinv[i] = rsqrtf((float)(val + 1));
    }
    if (i == 0) g_row_start[N_NODES] = N_EDGES;
}

// ---------------- CSR placement: 4 edges/thread ----------------------------
__global__ void place_kernel(const int* __restrict__ src,
                             const int* __restrict__ dst) {
    int t = blockIdx.x * blockDim.x + threadIdx.x;
    if (t >= N_EDGES / 4) return;
    int4 s = *(const int4*)(src + t * 4);
    int4 d = *(const int4*)(dst + t * 4);
    g_csr_src[atomicAdd(&g_pos[d.x], 1)] = s.x;
    g_csr_src[atomicAdd(&g_pos[d.y], 1)] = s.y;
    g_csr_src[atomicAdd(&g_pos[d.z], 1)] = s.z;
    g_csr_src[atomicAdd(&g_pos[d.w], 1)] = s.w;
}

// ---------------- SGEMM + fused dinv-scale + fp16 epilogue -----------------
// Gsh[row][:] = fp16(dinv[row] * (x[row,:] @ W12))   (waits on evDinv)
__global__ void gemmG_kernel(const float* __restrict__ X) {
    constexpr int BM = 128, BK = 8, BN = OUT_CH;
    constexpr int TX = BN / 8;            // 8
    __shared__ float sA[BK][BM];
    __shared__ float sB[BK][BN];
    const int tid = threadIdx.x;          // 128 threads
    const int tx = tid % TX, ty = tid / TX;
    const int row0 = blockIdx.x * BM;

    float acc[8][8] = {};
    for (int kc = 0; kc < IN_CH; kc += BK) {
#pragma unroll
        for (int v = 0; v < 2; v++) {
            int a = tid + v * 128;
            int row = a >> 1, kq = (a & 1) * 4;
            float4 val = make_float4(0.f, 0.f, 0.f, 0.f);
            if (row0 + row < N_NODES)
                val = *(const float4*)(X + (size_t)(row0 + row) * IN_CH + kc + kq);
            sA[kq + 0][row] = val.x; sA[kq + 1][row] = val.y;
            sA[kq + 2][row] = val.z; sA[kq + 3][row] = val.w;
        }
        {
            int k = tid >> 4, c4 = tid & 15;
            *(float4*)&sB[k][c4 * 4] =
                *(const float4*)(g_W12 + (size_t)(kc + k) * OUT_CH + c4 * 4);
        }
        __syncthreads();
#pragma unroll
        for (int k = 0; k < BK; k++) {
            float ra[8], rb[8];
#pragma unroll
            for (int i = 0; i < 8; i++) ra[i] = sA[k][ty * 8 + i];
#pragma unroll
            for (int j = 0; j < 8; j++) rb[j] = sB[k][tx * 8 + j];
#pragma unroll
            for (int i = 0; i < 8; i++)
#pragma unroll
                for (int j = 0; j < 8; j++) acc[i][j] += ra[i] * rb[j];
        }
        __syncthreads();
    }
#pragma unroll
    for (int i = 0; i < 8; i++) {
        int row = row0 + ty * 8 + i;
        if (row < N_NODES) {
            float di = g_dinv[row];
#pragma unroll
            for (int j = 0; j < 8; j += 4) {
                __half2 lo = __floats2half2_rn(acc[i][j] * di, acc[i][j + 1] * di);
                __half2 hi = __floats2half2_rn(acc[i][j + 2] * di, acc[i][j + 3] * di);
                __half* p = g_Gsh + (size_t)row * OUT_CH + tx * 8 + j;
                ((__half2*)p)[0] = lo;
                ((__half2*)p)[1] = hi;
            }
        }
    }
}

__device__ __forceinline__ float4 ld4h(const __half* p) {
    __half2 a = ((const __half2*)p)[0];
    __half2 b = ((const __half2*)p)[1];
    float2 fa = __half22float2(a), fb = __half22float2(b);
    return make_float4(fa.x, fa.y, fb.x, fb.y);
}

// ---------------- gather0: fp16 in, fp32 accumulate, fp16 out --------------
// h2sh = fp16( di^2*(sum Gsh) + di*c )   [h2s is pre-scaled by dinv]
__global__ void gather0_kernel() {
    constexpr int F = OUT_CH, TPN = F / 4;
    int g = blockIdx.x * blockDim.x + threadIdx.x;
    int node = g / TPN;
    int lane = g % TPN;
    if (node >= N_NODES) return;
    int l4 = lane * 4;
    const __half* H = g_Gsh;

    float4 acc = ld4h(H + (size_t)node * F + l4);    // self term

    int k  = g_row_start[node];
    int re = g_row_start[node + 1];
    for (; k + 7 < re; k += 8) {
        int s0 = __ldg(&g_csr_src[k]);     int s1 = __ldg(&g_csr_src[k + 1]);
        int s2 = __ldg(&g_csr_src[k + 2]); int s3 = __ldg(&g_csr_src[k + 3]);
        int s4 = __ldg(&g_csr_src[k + 4]); int s5 = __ldg(&g_csr_src[k + 5]);
        int s6 = __ldg(&g_csr_src[k + 6]); int s7 = __ldg(&g_csr_src[k + 7]);
        float4 v0 = ld4h(H + (size_t)s0 * F + l4);
        float4 v1 = ld4h(H + (size_t)s1 * F + l4);
        float4 v2 = ld4h(H + (size_t)s2 * F + l4);
        float4 v3 = ld4h(H + (size_t)s3 * F + l4);
        float4 v4 = ld4h(H + (size_t)s4 * F + l4);
        float4 v5 = ld4h(H + (size_t)s5 * F + l4);
        float4 v6 = ld4h(H + (size_t)s6 * F + l4);
        float4 v7 = ld4h(H + (size_t)s7 * F + l4);
        acc.x += ((v0.x + v1.x) + (v2.x + v3.x)) + ((v4.x + v5.x) + (v6.x + v7.x));
        acc.y += ((v0.y + v1.y) + (v2.y + v3.y)) + ((v4.y + v5.y) + (v6.y + v7.y));
        acc.z += ((v0.z + v1.z) + (v2.z + v3.z)) + ((v4.z + v5.z) + (v6.z + v7.z));
        acc.w += ((v0.w + v1.w) + (v2.w + v3.w)) + ((v4.w + v5.w) + (v6.w + v7.w));
    }
    for (; k < re; k++) {
        int s = __ldg(&g_csr_src[k]);
        float4 v = ld4h(H + (size_t)s * F + l4);
        acc.x += v.x; acc.y += v.y; acc.z += v.z; acc.w += v.w;
    }

    float di = g_dinv[node];
    float sc = di * di;
    float r0 = sc * acc.x + di * g_c[l4];
    float r1 = sc * acc.y + di * g_c[l4 + 1];
    float r2 = sc * acc.z + di * g_c[l4 + 2];
    float r3 = sc * acc.w + di * g_c[l4 + 3];
    __half* p = g_h2sh + (size_t)node * F + l4;
    ((__half2*)p)[0] = __floats2half2_rn(r0, r1);
    ((__half2*)p)[1] = __floats2half2_rn(r2, r3);
}

// ---------------- gather1: fp16 in, fp32 accumulate, fp32 out --------------
// out = di * (sum h2sh) + b2
__global__ void gather1_kernel(const float* __restrict__ b2,
                               float* __restrict__ Aout) {
    constexpr int F = OUT_CH, TPN = F / 4;
    int g = blockIdx.x * blockDim.x + threadIdx.x;
    int node = g / TPN;
    int lane = g % TPN;
    if (node >= N_NODES) return;
    int l4 = lane * 4;
    const __half* H = g_h2sh;

    float4 acc = ld4h(H + (size_t)node * F + l4);

    int k  = g_row_start[node];
    int re = g_row_start[node + 1];
    for (; k + 7 < re; k += 8) {
        int s0 = __ldg(&g_csr_src[k]);     int s1 = __ldg(&g_csr_src[k + 1]);
        int s2 = __ldg(&g_csr_src[k + 2]); int s3 = __ldg(&g_csr_src[k + 3]);
        int s4 = __ldg(&g_csr_src[k + 4]); int s5 = __ldg(&g_csr_src[k + 5]);
        int s6 = __ldg(&g_csr_src[k + 6]); int s7 = __ldg(&g_csr_src[k + 7]);
        float4 v0 = ld4h(H + (size_t)s0 * F + l4);
        float4 v1 = ld4h(H + (size_t)s1 * F + l4);
        float4 v2 = ld4h(H + (size_t)s2 * F + l4);
        float4 v3 = ld4h(H + (size_t)s3 * F + l4);
        float4 v4 = ld4h(H + (size_t)s4 * F + l4);
        float4 v5 = ld4h(H + (size_t)s5 * F + l4);
        float4 v6 = ld4h(H + (size_t)s6 * F + l4);
        float4 v7 = ld4h(H + (size_t)s7 * F + l4);
        acc.x += ((v0.x + v1.x) + (v2.x + v3.x)) + ((v4.x + v5.x) + (v6.x + v7.x));
        acc.y += ((v0.y + v1.y) + (v2.y + v3.y)) + ((v4.y + v5.y) + (v6.y + v7.y));
        acc.z += ((v0.z + v1.z) + (v2.z + v3.z)) + ((v4.z + v5.z) + (v6.z + v7.z));
        acc.w += ((v0.w + v1.w) + (v2.w + v3.w)) + ((v4.w + v5.w) + (v6.w + v7.w));
    }
    for (; k < re; k++) {
        int s = __ldg(&g_csr_src[k]);
        float4 v = ld4h(H + (size_t)s * F + l4);
        acc.x += v.x; acc.y += v.y; acc.z += v.z; acc.w += v.w;
    }

    float di = g_dinv[node];
    acc.x = di * acc.x + b2[l4];
    acc.y = di * acc.y + b2[l4 + 1];
    acc.z = di * acc.z + b2[l4 + 2];
    acc.w = di * acc.w + b2[l4 + 3];
    *(float4*)(Aout + (size_t)node * F + l4) = acc;
}

// ---------------- launch ---------------------------------------------------
extern "C" void kernel_launch(void* const* d_in, const int* in_sizes, int n_in,
                              void* d_out, int out_size) {
    const float* x   = (const float*)d_in[0];
    const int*   ei  = (const int*)d_in[1];   // int32 (JAX demotes int64)
    const float* W1  = (const float*)d_in[2];
    const float* b1  = (const float*)d_in[3];
    const float* W2  = (const float*)d_in[4];
    const float* b2  = (const float*)d_in[5];
    float*       out = (float*)d_out;

    const int* e_src = ei;
    const int* e_dst = ei + N_EDGES;
    const int  T = 256;

    cudaStream_t s2;
    cudaEvent_t  evFork, evDinv, evJoin;
    cudaStreamCreateWithFlags(&s2, cudaStreamNonBlocking);
    cudaEventCreateWithFlags(&evFork, cudaEventDisableTiming);
    cudaEventCreateWithFlags(&evDinv, cudaEventDisableTiming);
    cudaEventCreateWithFlags(&evJoin, cudaEventDisableTiming);

    cudaEventRecord(evFork, 0);
    cudaStreamWaitEvent(s2, evFork, 0);

    // side stream: CSR build (count -> fused scan -> place)
    count_deg_kernel<<<(N_EDGES / 4 + T - 1) / T, T, 0, s2>>>(e_dst);
    scan_fused_kernel<<<NCHUNK, 256, 0, s2>>>();
    cudaEventRecord(evDinv, s2);               // dinv + row_start ready
    place_kernel<<<(N_EDGES / 4 + T - 1) / T, T, 0, s2>>>(e_src, e_dst);
    cudaEventRecord(evJoin, s2);

    // main stream: w12 (split-K) ; gemmG fused with dinv-scale+fp16 epilogue
    w12_kernel<<<IN_CH + 1, 256>>>(W1, W2, b1);
    cudaStreamWaitEvent(0, evDinv, 0);         // epilogue needs dinv
    gemmG_kernel<<<(N_NODES + 127) / 128, 128>>>(x);

    // join: gathers need full CSR
    cudaStreamWaitEvent(0, evJoin, 0);
    gather0_kernel<<<(N_NODES * (OUT_CH / 4) + T - 1) / T, T>>>();
    gather1_kernel<<<(N_NODES * (OUT_CH / 4) + T - 1) / T, T>>>(b2, out);

    cudaEventDestroy(evFork);
    cudaEventDestroy(evDinv);
    cudaEventDestroy(evJoin);
    cudaStreamDestroy(s2);
}

// round 13
// speedup vs baseline: 1.1357x; 1.1357x over previous
#include <cuda_runtime.h>
#include <cuda_fp16.h>

#define N_NODES 50000
#define N_EDGES 800000
#define IN_CH   128
#define HID     128
#define OUT_CH  64
#define NCHUNK  ((N_NODES + 255) / 256)   // 196

// ---------------- device-global scratch ------------------------------------
__device__ float  g_W12[IN_CH * OUT_CH];             // W1 @ W2  (128x64)
__device__ __half g_Gsh [(size_t)N_NODES * OUT_CH];  // fp16(dinv .* (x@W12))
__device__ __half g_h2sh[(size_t)N_NODES * OUT_CH];  // fp16(dinv .* h2)
__device__ float  g_c[OUT_CH];                       // b1^T @ W2
__device__ float  g_dinv[N_NODES];
__device__ int    g_cnt[N_NODES];                    // in-degree (cleanup kernel)
__device__ int    g_pos[N_NODES];                    // placement cursor
__device__ int    g_row_start[N_NODES + 1];
__device__ int    g_csr_src[N_EDGES];
__device__ int    g_agg[NCHUNK];
__device__ volatile int g_flag[NCHUNK];              // cleared in count_deg

// ---------------- count: 4 edges/thread; block 0 clears scan flags ----------
__global__ void count_deg_kernel(const int* __restrict__ dst) {
    int t = blockIdx.x * blockDim.x + threadIdx.x;
    if (blockIdx.x == 0 && threadIdx.x < NCHUNK) g_flag[threadIdx.x] = 0;
    if (t < N_EDGES / 4) {
        int4 d = *(const int4*)(dst + t * 4);
        atomicAdd(&g_cnt[d.x], 1);
        atomicAdd(&g_cnt[d.y], 1);
        atomicAdd(&g_cnt[d.z], 1);
        atomicAdd(&g_cnt[d.w], 1);
    }
}

// ---------------- dinv (main stream, right after count) --------------------
__global__ void dinv_kernel() {
    int i = blockIdx.x * blockDim.x + threadIdx.x;
    if (i < N_NODES) g_dinv[i] = rsqrtf((float)(g_cnt[i] + 1));
}

// ---------------- cleanup: zero g_cnt for next graph replay ----------------
__global__ void cleanup_kernel() {
    int i = blockIdx.x * blockDim.x + threadIdx.x;
    if (i < N_NODES) g_cnt[i] = 0;
}

// ---------------- w12: split-K, one block per output row -------------------
__global__ void w12_kernel(const float* __restrict__ W1,
                           const float* __restrict__ W2,
                           const float* __restrict__ b1) {
    __shared__ float part[4][OUT_CH];
    const int k = blockIdx.x;            // 0..128
    const int j = threadIdx.x & 63;
    const int q = threadIdx.x >> 6;      // 0..3
    const float* row = (k < IN_CH) ? (W1 + (size_t)k * HID) : b1;

    float s = 0.f;
#pragma unroll
    for (int t = 0; t < 32; t++) {
        int kk = q * 32 + t;
        s += __ldg(&row[kk]) * __ldg(&W2[(size_t)kk * OUT_CH + j]);
    }
    part[q][j] = s;
    __syncthreads();
    if (q == 0) {
        float v = part[0][j] + part[1][j] + part[2][j] + part[3][j];
        if (k < IN_CH) g_W12[k * OUT_CH + j] = v;
        else           g_c[j] = v;
    }
}

// ---------------- fused single-pass scan (publish-all, wait-all) -----------
__global__ void scan_fused_kernel() {
    __shared__ int s[256];
    __shared__ int pre[256];
    const int tid = threadIdx.x;
    const int chunk = blockIdx.x;
    const int i = chunk * 256 + tid;

    int val = (i < N_NODES) ? g_cnt[i] : 0;
    s[tid] = val;
    __syncthreads();
#pragma unroll
    for (int off = 1; off < 256; off <<= 1) {
        int t = (tid >= off) ? s[tid - off] : 0;
        __syncthreads();
        s[tid] += t;
        __syncthreads();
    }
    int incl = s[tid];

    if (tid == 0) {
        g_agg[chunk] = s[255];
        __threadfence();
        g_flag[chunk] = 1;
    }

    int my = 0;
    if (tid < chunk) {
        while (g_flag[tid] == 0) { }
        __threadfence();
        my = g_agg[tid];
    }
    __syncthreads();
    pre[tid] = my;
    __syncthreads();
#pragma unroll
    for (int off = 128; off > 0; off >>= 1) {
        if (tid < off) pre[tid] += pre[tid + off];
        __syncthreads();
    }
    int chunk_off = pre[0];

    if (i < N_NODES) {
        int rs = chunk_off + incl - val;
        g_row_start[i] = rs;
        g_pos[i]       = rs;
    }
    if (i == 0) g_row_start[N_NODES] = N_EDGES;
}

// ---------------- CSR placement: 4 edges/thread ----------------------------
__global__ void place_kernel(const int* __restrict__ src,
                             const int* __restrict__ dst) {
    int t = blockIdx.x * blockDim.x + threadIdx.x;
    if (t >= N_EDGES / 4) return;
    int4 s = *(const int4*)(src + t * 4);
    int4 d = *(const int4*)(dst + t * 4);
    g_csr_src[atomicAdd(&g_pos[d.x], 1)] = s.x;
    g_csr_src[atomicAdd(&g_pos[d.y], 1)] = s.y;
    g_csr_src[atomicAdd(&g_pos[d.z], 1)] = s.z;
    g_csr_src[atomicAdd(&g_pos[d.w], 1)] = s.w;
}

// ---------------- SGEMM + fused dinv-scale + fp16 epilogue -----------------
__global__ void gemmG_kernel(const float* __restrict__ X) {
    constexpr int BM = 128, BK = 8, BN = OUT_CH;
    constexpr int TX = BN / 8;            // 8
    __shared__ float sA[BK][BM];
    __shared__ float sB[BK][BN];
    const int tid = threadIdx.x;          // 128 threads
    const int tx = tid % TX, ty = tid / TX;
    const int row0 = blockIdx.x * BM;

    float acc[8][8] = {};
    for (int kc = 0; kc < IN_CH; kc += BK) {
#pragma unroll
        for (int v = 0; v < 2; v++) {
            int a = tid + v * 128;
            int row = a >> 1, kq = (a & 1) * 4;
            float4 val = make_float4(0.f, 0.f, 0.f, 0.f);
            if (row0 + row < N_NODES)
                val = *(const float4*)(X + (size_t)(row0 + row) * IN_CH + kc + kq);
            sA[kq + 0][row] = val.x; sA[kq + 1][row] = val.y;
            sA[kq + 2][row] = val.z; sA[kq + 3][row] = val.w;
        }
        {
            int k = tid >> 4, c4 = tid & 15;
            *(float4*)&sB[k][c4 * 4] =
                *(const float4*)(g_W12 + (size_t)(kc + k) * OUT_CH + c4 * 4);
        }
        __syncthreads();
#pragma unroll
        for (int k = 0; k < BK; k++) {
            float ra[8], rb[8];
#pragma unroll
            for (int i = 0; i < 8; i++) ra[i] = sA[k][ty * 8 + i];
#pragma unroll
            for (int j = 0; j < 8; j++) rb[j] = sB[k][tx * 8 + j];
#pragma unroll
            for (int i = 0; i < 8; i++)
#pragma unroll
                for (int j = 0; j < 8; j++) acc[i][j] += ra[i] * rb[j];
        }
        __syncthreads();
    }
#pragma unroll
    for (int i = 0; i < 8; i++) {
        int row = row0 + ty * 8 + i;
        if (row < N_NODES) {
            float di = g_dinv[row];
#pragma unroll
            for (int j = 0; j < 8; j += 4) {
                __half2 lo = __floats2half2_rn(acc[i][j] * di, acc[i][j + 1] * di);
                __half2 hi = __floats2half2_rn(acc[i][j + 2] * di, acc[i][j + 3] * di);
                __half* p = g_Gsh + (size_t)row * OUT_CH + tx * 8 + j;
                ((__half2*)p)[0] = lo;
                ((__half2*)p)[1] = hi;
            }
        }
    }
}

__device__ __forceinline__ float4 ld4h(const __half* p) {
    __half2 a = ((const __half2*)p)[0];
    __half2 b = ((const __half2*)p)[1];
    float2 fa = __half22float2(a), fb = __half22float2(b);
    return make_float4(fa.x, fa.y, fb.x, fb.y);
}

// ---------------- gather0: fp16 in, fp32 accumulate, fp16 out --------------
__global__ void gather0_kernel() {
    constexpr int F = OUT_CH, TPN = F / 4;
    int g = blockIdx.x * blockDim.x + threadIdx.x;
    int node = g / TPN;
    int lane = g % TPN;
    if (node >= N_NODES) return;
    int l4 = lane * 4;
    const __half* H = g_Gsh;

    float4 acc = ld4h(H + (size_t)node * F + l4);    // self term

    int k  = g_row_start[node];
    int re = g_row_start[node + 1];
    for (; k + 7 < re; k += 8) {
        int s0 = __ldg(&g_csr_src[k]);     int s1 = __ldg(&g_csr_src[k + 1]);
        int s2 = __ldg(&g_csr_src[k + 2]); int s3 = __ldg(&g_csr_src[k + 3]);
        int s4 = __ldg(&g_csr_src[k + 4]); int s5 = __ldg(&g_csr_src[k + 5]);
        int s6 = __ldg(&g_csr_src[k + 6]); int s7 = __ldg(&g_csr_src[k + 7]);
        float4 v0 = ld4h(H + (size_t)s0 * F + l4);
        float4 v1 = ld4h(H + (size_t)s1 * F + l4);
        float4 v2 = ld4h(H + (size_t)s2 * F + l4);
        float4 v3 = ld4h(H + (size_t)s3 * F + l4);
        float4 v4 = ld4h(H + (size_t)s4 * F + l4);
        float4 v5 = ld4h(H + (size_t)s5 * F + l4);
        float4 v6 = ld4h(H + (size_t)s6 * F + l4);
        float4 v7 = ld4h(H + (size_t)s7 * F + l4);
        acc.x += ((v0.x + v1.x) + (v2.x + v3.x)) + ((v4.x + v5.x) + (v6.x + v7.x));
        acc.y += ((v0.y + v1.y) + (v2.y + v3.y)) + ((v4.y + v5.y) + (v6.y + v7.y));
        acc.z += ((v0.z + v1.z) + (v2.z + v3.z)) + ((v4.z + v5.z) + (v6.z + v7.z));
        acc.w += ((v0.w + v1.w) + (v2.w + v3.w)) + ((v4.w + v5.w) + (v6.w + v7.w));
    }
    for (; k < re; k++) {
        int s = __ldg(&g_csr_src[k]);
        float4 v = ld4h(H + (size_t)s * F + l4);
        acc.x += v.x; acc.y += v.y; acc.z += v.z; acc.w += v.w;
    }

    float di = g_dinv[node];
    float sc = di * di;
    float r0 = sc * acc.x + di * g_c[l4];
    float r1 = sc * acc.y + di * g_c[l4 + 1];
    float r2 = sc * acc.z + di * g_c[l4 + 2];
    float r3 = sc * acc.w + di * g_c[l4 + 3];
    __half* p = g_h2sh + (size_t)node * F + l4;
    ((__half2*)p)[0] = __floats2half2_rn(r0, r1);
    ((__half2*)p)[1] = __floats2half2_rn(r2, r3);
}

// ---------------- gather1: fp16 in, fp32 accumulate, fp32 out --------------
__global__ void gather1_kernel(const float* __restrict__ b2,
                               float* __restrict__ Aout) {
    constexpr int F = OUT_CH, TPN = F / 4;
    int g = blockIdx.x * blockDim.x + threadIdx.x;
    int node = g / TPN;
    int lane = g % TPN;
    if (node >= N_NODES) return;
    int l4 = lane * 4;
    const __half* H = g_h2sh;

    float4 acc = ld4h(H + (size_t)node * F + l4);

    int k  = g_row_start[node];
    int re = g_row_start[node + 1];
    for (; k + 7 < re; k += 8) {
        int s0 = __ldg(&g_csr_src[k]);     int s1 = __ldg(&g_csr_src[k + 1]);
        int s2 = __ldg(&g_csr_src[k + 2]); int s3 = __ldg(&g_csr_src[k + 3]);
        int s4 = __ldg(&g_csr_src[k + 4]); int s5 = __ldg(&g_csr_src[k + 5]);
        int s6 = __ldg(&g_csr_src[k + 6]); int s7 = __ldg(&g_csr_src[k + 7]);
        float4 v0 = ld4h(H + (size_t)s0 * F + l4);
        float4 v1 = ld4h(H + (size_t)s1 * F + l4);
        float4 v2 = ld4h(H + (size_t)s2 * F + l4);
        float4 v3 = ld4h(H + (size_t)s3 * F + l4);
        float4 v4 = ld4h(H + (size_t)s4 * F + l4);
        float4 v5 = ld4h(H + (size_t)s5 * F + l4);
        float4 v6 = ld4h(H + (size_t)s6 * F + l4);
        float4 v7 = ld4h(H + (size_t)s7 * F + l4);
        acc.x += ((v0.x + v1.x) + (v2.x + v3.x)) + ((v4.x + v5.x) + (v6.x + v7.x));
        acc.y += ((v0.y + v1.y) + (v2.y + v3.y)) + ((v4.y + v5.y) + (v6.y + v7.y));
        acc.z += ((v0.z + v1.z) + (v2.z + v3.z)) + ((v4.z + v5.z) + (v6.z + v7.z));
        acc.w += ((v0.w + v1.w) + (v2.w + v3.w)) + ((v4.w + v5.w) + (v6.w + v7.w));
    }
    for (; k < re; k++) {
        int s = __ldg(&g_csr_src[k]);
        float4 v = ld4h(H + (size_t)s * F + l4);
        acc.x += v.x; acc.y += v.y; acc.z += v.z; acc.w += v.w;
    }

    float di = g_dinv[node];
    acc.x = di * acc.x + b2[l4];
    acc.y = di * acc.y + b2[l4 + 1];
    acc.z = di * acc.z + b2[l4 + 2];
    acc.w = di * acc.w + b2[l4 + 3];
    *(float4*)(Aout + (size_t)node * F + l4) = acc;
}

// ---------------- launch ---------------------------------------------------
extern "C" void kernel_launch(void* const* d_in, const int* in_sizes, int n_in,
                              void* d_out, int out_size) {
    const float* x   = (const float*)d_in[0];
    const int*   ei  = (const int*)d_in[1];   // int32 (JAX demotes int64)
    const float* W1  = (const float*)d_in[2];
    const float* b1  = (const float*)d_in[3];
    const float* W2  = (const float*)d_in[4];
    const float* b2  = (const float*)d_in[5];
    float*       out = (float*)d_out;

    const int* e_src = ei;
    const int* e_dst = ei + N_EDGES;
    const int  T = 256;

    cudaStream_t s2;
    cudaEvent_t  evFork, evCnt, evDinvDone, evJoin, evClean;
    cudaStreamCreateWithFlags(&s2, cudaStreamNonBlocking);
    cudaEventCreateWithFlags(&evFork, cudaEventDisableTiming);
    cudaEventCreateWithFlags(&evCnt, cudaEventDisableTiming);
    cudaEventCreateWithFlags(&evDinvDone, cudaEventDisableTiming);
    cudaEventCreateWithFlags(&evJoin, cudaEventDisableTiming);
    cudaEventCreateWithFlags(&evClean, cudaEventDisableTiming);

    cudaEventRecord(evFork, 0);
    cudaStreamWaitEvent(s2, evFork, 0);

    // side stream: count -> (evCnt) -> scan -> place -> (evJoin) -> cleanup
    count_deg_kernel<<<(N_EDGES / 4 + T - 1) / T, T, 0, s2>>>(e_dst);
    cudaEventRecord(evCnt, s2);                // g_cnt complete
    scan_fused_kernel<<<NCHUNK, 256, 0, s2>>>();
    place_kernel<<<(N_EDGES / 4 + T - 1) / T, T, 0, s2>>>(e_src, e_dst);
    cudaEventRecord(evJoin, s2);

    // main stream: w12 (‖ count); dinv as soon as counts land; then gemmG
    w12_kernel<<<IN_CH + 1, 256>>>(W1, W2, b1);
    cudaStreamWaitEvent(0, evCnt, 0);
    dinv_kernel<<<(N_NODES + T - 1) / T, T>>>();
    cudaEventRecord(evDinvDone, 0);
    gemmG_kernel<<<(N_NODES + 127) / 128, 128>>>(x);

    // cleanup g_cnt on side stream (after scan + dinv have read it);
    // overlaps the gathers, then is re-joined below.
    cudaStreamWaitEvent(s2, evDinvDone, 0);
    cleanup_kernel<<<(N_NODES + T - 1) / T, T, 0, s2>>>();
    cudaEventRecord(evClean, s2);

    // join: gathers need full CSR
    cudaStreamWaitEvent(0, evJoin, 0);
    gather0_kernel<<<(N_NODES * (OUT_CH / 4) + T - 1) / T, T>>>();
    gather1_kernel<<<(N_NODES * (OUT_CH / 4) + T - 1) / T, T>>>(b2, out);

    // rejoin the cleanup branch so the capture ends with a single stream
    cudaStreamWaitEvent(0, evClean, 0);

    cudaEventDestroy(evFork);
    cudaEventDestroy(evCnt);
    cudaEventDestroy(evDinvDone);
    cudaEventDestroy(evJoin);
    cudaEventDestroy(evClean);
    cudaStreamDestroy(s2);
}